// round 9
// baseline (speedup 1.0000x reference)
#include <cuda_runtime.h>
#include <math.h>
#include <float.h>

// ---------------------------------------------------------------------------
// Problem constants
// ---------------------------------------------------------------------------
constexpr int N_   = 50000;
constexpr int IN_  = 128;
constexpr int HID_ = 64;
constexpr int H_   = 4;
constexpr int F_   = 256;    // H*D
constexpr int OUT_ = 16;
constexpr int SAH_ = 128;
constexpr int EMAX_ = 800000;

constexpr size_t NF = (size_t)N_ * F_;
constexpr int SC4N = 4 * N_;
constexpr int SCB4 = (SC4N + 255) / 256;
constexpr int WSB_N = (N_ + 127) / 128;
constexpr int POSTB_N = (N_ + 63) / 64;
// post_tc smem: sA 64 rows * 268 + sB 256 cols * 68 + bias 256
constexpr int POST_SMEM = (64 * 268 + 256 * 68 + 256) * 4;   // 139264 B

// ---------------------------------------------------------------------------
// Device scratch
// ---------------------------------------------------------------------------
__device__ float g_x[(size_t)N_ * HID_];
__device__ __align__(16) float g_el[N_ * H_];
__device__ __align__(16) float g_er[N_ * H_];
__device__ float g_agg[NF];                        // [n][k*4+h]
__device__ float g_emb[6 * NF];
__device__ float g_hl[2 * NF];
__device__ float g_hfin[NF];
__device__ float g_wsum[3][4];
__device__ float g_beta[3][4];
__device__ unsigned int g_W1bf[(SAH_ * F_) / 2];   // bf16x2, [pair p][col c]: p=f/2

// Batched CSR scratch
__device__ int g_cnt4[SC4N];
__device__ int g_cursor4[SC4N];
__device__ int g_prefix[SC4N + 1];
__device__ int g_esrcF[4 * EMAX_];
__device__ int g_bsum[SCB4];
__device__ int g_boff[SCB4];

struct G4 { const int* s[4]; const int* d[4]; int E[4]; };

// ---------------------------------------------------------------------------
// Low-level helpers
// ---------------------------------------------------------------------------
__device__ __forceinline__ unsigned int f2tf32(float f) {
    unsigned int r;
    asm("cvt.rna.tf32.f32 %0, %1;" : "=r"(r) : "f"(f));
    return r;
}
__device__ __forceinline__ unsigned int pack_bf2(float lo, float hi) {
    unsigned int r;
    asm("cvt.rn.bf16x2.f32 %0, %1, %2;" : "=r"(r) : "f"(hi), "f"(lo));
    return r;
}
__device__ __forceinline__ float tanh_fast(float x) {
    float r;
    asm("tanh.approx.f32 %0, %1;" : "=f"(r) : "f"(x));
    return r;
}
__device__ __forceinline__ void mma_tf32(float& d0, float& d1, float& d2, float& d3,
                                         unsigned int a0, unsigned int a1,
                                         unsigned int a2, unsigned int a3,
                                         unsigned int b0, unsigned int b1) {
    asm("mma.sync.aligned.m16n8k8.row.col.f32.tf32.tf32.f32 "
        "{%0,%1,%2,%3}, {%4,%5,%6,%7}, {%8,%9}, {%0,%1,%2,%3};"
        : "+f"(d0), "+f"(d1), "+f"(d2), "+f"(d3)
        : "r"(a0), "r"(a1), "r"(a2), "r"(a3), "r"(b0), "r"(b1));
}
__device__ __forceinline__ void mma_bf16(float& d0, float& d1, float& d2, float& d3,
                                         unsigned int a0, unsigned int a1,
                                         unsigned int a2, unsigned int a3,
                                         unsigned int b0, unsigned int b1) {
    asm("mma.sync.aligned.m16n8k16.row.col.f32.bf16.bf16.f32 "
        "{%0,%1,%2,%3}, {%4,%5,%6,%7}, {%8,%9}, {%0,%1,%2,%3};"
        : "+f"(d0), "+f"(d1), "+f"(d2), "+f"(d3)
        : "r"(a0), "r"(a1), "r"(a2), "r"(a3), "r"(b0), "r"(b1));
}

// ---------------------------------------------------------------------------
// x = h @ fc_W   [N,128] @ [128,64]
// ---------------------------------------------------------------------------
__global__ void k_fc(const float* __restrict__ h, const float* __restrict__ W) {
    __shared__ __align__(16) float sW[IN_ * HID_];
    __shared__ __align__(16) float sh[16 * IN_];
    int tid = threadIdx.x;
    for (int i = tid; i < IN_ * HID_; i += 256) sW[i] = W[i];
    int row0 = blockIdx.x * 16;
    for (int i = tid; i < 16 * IN_; i += 256) {
        int r = i >> 7, k = i & 127;
        sh[i] = (row0 + r < N_) ? h[(size_t)(row0 + r) * IN_ + k] : 0.f;
    }
    __syncthreads();
    int col = tid & 63;
    for (int rr = tid >> 6; rr < 16; rr += 4) {
        float acc = 0.f;
#pragma unroll
        for (int k = 0; k < IN_; k += 4) {
            float4 hv = *(const float4*)&sh[rr * IN_ + k];
            acc += hv.x * sW[k * HID_ + col] + hv.y * sW[(k + 1) * HID_ + col]
                 + hv.z * sW[(k + 2) * HID_ + col] + hv.w * sW[(k + 3) * HID_ + col];
        }
        if (row0 + rr < N_) g_x[(size_t)(row0 + rr) * HID_ + col] = acc;
    }
}

// ---------------------------------------------------------------------------
// Fused prew + eler: each block computes wtab = {W·al, W·ar} locally, then
// 256 nodes of el/er.  Block: 256 threads, 196 blocks.
// ---------------------------------------------------------------------------
__global__ void __launch_bounds__(256) k_eler3f(const float* __restrict__ W,
                                                const float* __restrict__ al,
                                                const float* __restrict__ ar) {
    __shared__ float swt[HID_ * 8];   // [k][o]: o<4 W·al, o>=4 W·ar
    int tid = threadIdx.x;
    {
        int k = tid >> 2, h = tid & 3;
        const float* wr = W + k * F_ + h * 64;
        const float* alr = al + h * 64;
        const float* arr = ar + h * 64;
        float a = 0.f, b = 0.f;
#pragma unroll 8
        for (int d = 0; d < 64; d++) { a += wr[d] * alr[d]; b += wr[d] * arr[d]; }
        swt[k * 8 + h] = a;
        swt[k * 8 + 4 + h] = b;
    }
    __syncthreads();
    int o = tid & 7;
    int n0 = blockIdx.x * 256;
    for (int pass = 0; pass < 8; pass++) {
        int n = n0 + pass * 32 + (tid >> 3);
        if (n >= N_) break;
        const float4* xr = (const float4*)(g_x + (size_t)n * HID_);
        float acc = 0.f;
#pragma unroll
        for (int q = 0; q < 16; q++) {
            float4 v = xr[q];
            acc += v.x * swt[(q * 4 + 0) * 8 + o] + v.y * swt[(q * 4 + 1) * 8 + o]
                 + v.z * swt[(q * 4 + 2) * 8 + o] + v.w * swt[(q * 4 + 3) * 8 + o];
        }
        if (o < 4) g_el[n * 4 + o] = acc;
        else       g_er[n * 4 + (o - 4)] = acc;
    }
}

// ---------------------------------------------------------------------------
// Batched CSR construction
// ---------------------------------------------------------------------------
__global__ void k_zerocnt4() {
    int i = blockIdx.x * 256 + threadIdx.x;
    if (i < SC4N) g_cnt4[i] = 0;
}
__global__ void k_hist4(G4 a) {
    int g = blockIdx.y;
    int i = blockIdx.x * 256 + threadIdx.x;
    if (i < a.E[g]) atomicAdd(&g_cnt4[g * N_ + a.d[g][i]], 1);
}

template <int NW>
__device__ __forceinline__ int scan_excl(int v, int tid, int* total) {
    int lane = tid & 31, w = tid >> 5;
    int x = v;
#pragma unroll
    for (int o = 1; o < 32; o <<= 1) {
        int y = __shfl_up_sync(0xffffffffu, x, o);
        if (lane >= o) x += y;
    }
    __shared__ int ws[NW];
    if (lane == 31) ws[w] = x;
    __syncthreads();
    if (w == 0) {
        int s = (lane < NW) ? ws[lane] : 0;
#pragma unroll
        for (int o = 1; o < NW; o <<= 1) {
            int y = __shfl_up_sync(0xffffffffu, s, o);
            if (lane >= o) s += y;
        }
        if (lane < NW) ws[lane] = s;
    }
    __syncthreads();
    int base = (w > 0) ? ws[w - 1] : 0;
    *total = ws[NW - 1];
    return base + x - v;
}

__global__ void k_scan1b() {
    int tid = threadIdx.x, b = blockIdx.x;
    int i = b * 256 + tid;
    int v = (i < SC4N) ? g_cnt4[i] : 0;
    int total;
    int excl = scan_excl<8>(v, tid, &total);
    if (i < SC4N) g_prefix[i] = excl;
    if (tid == 0) g_bsum[b] = total;
}
__global__ void k_scan2b() {
    int tid = threadIdx.x;
    int v = (tid < SCB4) ? g_bsum[tid] : 0;
    int total;
    int excl = scan_excl<32>(v, tid, &total);
    if (tid < SCB4) g_boff[tid] = excl;
    if (tid == 0) g_prefix[SC4N] = total;
}
__global__ void k_scan3b() {
    int i = blockIdx.x * 256 + threadIdx.x;
    if (i < SC4N) {
        int r = g_prefix[i] + g_boff[i >> 8];
        g_prefix[i] = r;
        g_cursor4[i] = r;
    }
}
__global__ void k_scatter4(G4 a) {
    int g = blockIdx.y;
    int i = blockIdx.x * 256 + threadIdx.x;
    if (i >= a.E[g]) return;
    int d = a.d[g][i];
    int pos = atomicAdd(&g_cursor4[g * N_ + d], 1);
    g_esrcF[pos] = a.s[g][i];
}

// ---------------------------------------------------------------------------
// x-space gather-accumulate
// ---------------------------------------------------------------------------
__device__ __forceinline__ void gather_acc2(const int* __restrict__ ssrc,
                                            const float4* __restrict__ salpha,
                                            int cnt, int lane, float acc[8]) {
    int i = 0;
    for (; i + 4 <= cnt; i += 4) {
        int s0 = ssrc[i], s1 = ssrc[i + 1], s2 = ssrc[i + 2], s3 = ssrc[i + 3];
        float4 a0 = salpha[i], a1 = salpha[i + 1], a2 = salpha[i + 2], a3 = salpha[i + 3];
        float2 x0 = *(const float2*)(g_x + (size_t)s0 * HID_ + lane * 2);
        float2 x1 = *(const float2*)(g_x + (size_t)s1 * HID_ + lane * 2);
        float2 x2 = *(const float2*)(g_x + (size_t)s2 * HID_ + lane * 2);
        float2 x3 = *(const float2*)(g_x + (size_t)s3 * HID_ + lane * 2);
        acc[0] += a0.x * x0.x; acc[1] += a0.x * x0.y;
        acc[2] += a0.y * x0.x; acc[3] += a0.y * x0.y;
        acc[4] += a0.z * x0.x; acc[5] += a0.z * x0.y;
        acc[6] += a0.w * x0.x; acc[7] += a0.w * x0.y;
        acc[0] += a1.x * x1.x; acc[1] += a1.x * x1.y;
        acc[2] += a1.y * x1.x; acc[3] += a1.y * x1.y;
        acc[4] += a1.z * x1.x; acc[5] += a1.z * x1.y;
        acc[6] += a1.w * x1.x; acc[7] += a1.w * x1.y;
        acc[0] += a2.x * x2.x; acc[1] += a2.x * x2.y;
        acc[2] += a2.y * x2.x; acc[3] += a2.y * x2.y;
        acc[4] += a2.z * x2.x; acc[5] += a2.z * x2.y;
        acc[6] += a2.w * x2.x; acc[7] += a2.w * x2.y;
        acc[0] += a3.x * x3.x; acc[1] += a3.x * x3.y;
        acc[2] += a3.y * x3.x; acc[3] += a3.y * x3.y;
        acc[4] += a3.z * x3.x; acc[5] += a3.z * x3.y;
        acc[6] += a3.w * x3.x; acc[7] += a3.w * x3.y;
    }
    for (; i < cnt; i++) {
        int s = ssrc[i];
        float4 a = salpha[i];
        float2 xv = *(const float2*)(g_x + (size_t)s * HID_ + lane * 2);
        acc[0] += a.x * xv.x; acc[1] += a.x * xv.y;
        acc[2] += a.y * xv.x; acc[3] += a.y * xv.y;
        acc[4] += a.z * xv.x; acc[5] += a.z * xv.y;
        acc[6] += a.w * xv.x; acc[7] += a.w * xv.y;
    }
}

// ---------------------------------------------------------------------------
// GAT conv in x-space — WARP per dst node. Writes agg[n][k*4+h].
// ---------------------------------------------------------------------------
__global__ void __launch_bounds__(256) k_conv2(int gi) {
    __shared__ int s_src[8][32];
    __shared__ __align__(16) float4 s_alpha[8][32];

    int tid = threadIdx.x, lane = tid & 31, w = tid >> 5;
    int n = blockIdx.x * 8 + w;
    if (n >= N_) return;

    int e0 = g_prefix[gi * N_ + n], e1 = g_prefix[gi * N_ + n + 1];
    int deg = e1 - e0;

    float4 ern = *(const float4*)(g_er + n * 4);
    float acc[8] = {0.f, 0.f, 0.f, 0.f, 0.f, 0.f, 0.f, 0.f};

    if (deg > 0 && deg <= 32) {
        int s = -1;
        float v0 = -FLT_MAX, v1 = -FLT_MAX, v2 = -FLT_MAX, v3 = -FLT_MAX;
        if (lane < deg) {
            s = g_esrcF[e0 + lane];
            float4 els = *(const float4*)(g_el + s * 4);
            v0 = els.x + ern.x; v0 = v0 > 0.f ? v0 : 0.2f * v0;
            v1 = els.y + ern.y; v1 = v1 > 0.f ? v1 : 0.2f * v1;
            v2 = els.z + ern.z; v2 = v2 > 0.f ? v2 : 0.2f * v2;
            v3 = els.w + ern.w; v3 = v3 > 0.f ? v3 : 0.2f * v3;
        }
        float m0 = v0, m1 = v1, m2 = v2, m3 = v3;
#pragma unroll
        for (int o = 16; o > 0; o >>= 1) {
            m0 = fmaxf(m0, __shfl_xor_sync(0xffffffffu, m0, o));
            m1 = fmaxf(m1, __shfl_xor_sync(0xffffffffu, m1, o));
            m2 = fmaxf(m2, __shfl_xor_sync(0xffffffffu, m2, o));
            m3 = fmaxf(m3, __shfl_xor_sync(0xffffffffu, m3, o));
        }
        float e0f = (lane < deg) ? __expf(v0 - m0) : 0.f;
        float e1f = (lane < deg) ? __expf(v1 - m1) : 0.f;
        float e2f = (lane < deg) ? __expf(v2 - m2) : 0.f;
        float e3f = (lane < deg) ? __expf(v3 - m3) : 0.f;
        float s0 = e0f, s1 = e1f, s2 = e2f, s3 = e3f;
#pragma unroll
        for (int o = 16; o > 0; o >>= 1) {
            s0 += __shfl_xor_sync(0xffffffffu, s0, o);
            s1 += __shfl_xor_sync(0xffffffffu, s1, o);
            s2 += __shfl_xor_sync(0xffffffffu, s2, o);
            s3 += __shfl_xor_sync(0xffffffffu, s3, o);
        }
        s_src[w][lane] = s;
        s_alpha[w][lane] = make_float4(e0f / s0, e1f / s1, e2f / s2, e3f / s3);
        __syncwarp();
        gather_acc2(s_src[w], s_alpha[w], deg, lane, acc);
    } else if (deg > 32) {
        float mx[4] = {-FLT_MAX, -FLT_MAX, -FLT_MAX, -FLT_MAX};
        float sm[4] = {0.f, 0.f, 0.f, 0.f};
        for (int e = e0 + lane; e < e1; e += 32) {
            int s = g_esrcF[e];
            float4 els = *(const float4*)(g_el + s * 4);
            float v[4];
            v[0] = els.x + ern.x; v[1] = els.y + ern.y;
            v[2] = els.z + ern.z; v[3] = els.w + ern.w;
#pragma unroll
            for (int h = 0; h < 4; h++) {
                float vv = v[h] > 0.f ? v[h] : 0.2f * v[h];
                float nm = fmaxf(mx[h], vv);
                sm[h] = sm[h] * __expf(mx[h] - nm) + __expf(vv - nm);
                mx[h] = nm;
            }
        }
#pragma unroll
        for (int h = 0; h < 4; h++) {
#pragma unroll
            for (int o = 16; o > 0; o >>= 1) {
                float om = __shfl_xor_sync(0xffffffffu, mx[h], o);
                float os = __shfl_xor_sync(0xffffffffu, sm[h], o);
                float nm = fmaxf(mx[h], om);
                sm[h] = sm[h] * __expf(mx[h] - nm) + os * __expf(om - nm);
                mx[h] = nm;
            }
        }
        float inv[4];
#pragma unroll
        for (int h = 0; h < 4; h++) inv[h] = 1.f / sm[h];

        for (int base = 0; base < deg; base += 32) {
            int cnt = min(32, deg - base);
            int s = -1;
            float4 al4 = make_float4(0.f, 0.f, 0.f, 0.f);
            if (lane < cnt) {
                s = g_esrcF[e0 + base + lane];
                float4 els = *(const float4*)(g_el + s * 4);
                float v0 = els.x + ern.x; v0 = v0 > 0.f ? v0 : 0.2f * v0;
                float v1 = els.y + ern.y; v1 = v1 > 0.f ? v1 : 0.2f * v1;
                float v2 = els.z + ern.z; v2 = v2 > 0.f ? v2 : 0.2f * v2;
                float v3 = els.w + ern.w; v3 = v3 > 0.f ? v3 : 0.2f * v3;
                al4 = make_float4(__expf(v0 - mx[0]) * inv[0], __expf(v1 - mx[1]) * inv[1],
                                  __expf(v2 - mx[2]) * inv[2], __expf(v3 - mx[3]) * inv[3]);
            }
            __syncwarp();
            s_src[w][lane] = s;
            s_alpha[w][lane] = al4;
            __syncwarp();
            gather_acc2(s_src[w], s_alpha[w], cnt, lane, acc);
        }
    }

    float4* op = (float4*)(g_agg + (size_t)n * F_ + (lane * 2) * 4);
    op[0] = make_float4(acc[0], acc[2], acc[4], acc[6]);
    op[1] = make_float4(acc[1], acc[3], acc[5], acc[7]);
}

// ---------------------------------------------------------------------------
// Post-GEMM on tensor cores (tf32): emb[n,h,d] = elu(sum_k agg[n,h,k]W[k,h,d]+b)
// Block: 64 nodes x 256 cols; 8 warps: warp = (row-tile w&3, col-half w>>2).
// ---------------------------------------------------------------------------
__global__ void __launch_bounds__(256) k_post_tc(const float* __restrict__ W,
                                                 const float* __restrict__ bias,
                                                 int slot) {
    extern __shared__ __align__(16) unsigned int smemu[];
    unsigned int* sA = smemu;                      // [64][268]: r*268 + h*67 + k
    unsigned int* sB = smemu + 64 * 268;           // [256][68]: c*68 + k
    float* s_bias = (float*)(smemu + 64 * 268 + 256 * 68);

    int tid = threadIdx.x, lane = tid & 31, w = tid >> 5;
    int n0 = blockIdx.x * 64;

    if (tid < 256) s_bias[tid] = bias[tid];
    // stage A: agg rows (fp32 -> tf32), reorganized to per-head [r][h][k]
    for (int i = tid; i < 64 * 256; i += 256) {
        int r = i >> 8, j = i & 255;
        int k = j >> 2, h = j & 3;
        float v = (n0 + r < N_) ? g_agg[(size_t)(n0 + r) * F_ + j] : 0.f;
        sA[r * 268 + h * 67 + k] = f2tf32(v);
    }
    // stage B: W[k][c] -> sB[c][k] (tf32)
    for (int i = tid; i < 64 * 256; i += 256) {
        int k = i >> 8, c = i & 255;
        sB[c * 68 + k] = f2tf32(W[k * F_ + c]);
    }
    __syncthreads();

    int g4 = lane >> 2, tg = lane & 3;
    int r0 = (w & 3) * 16;
    int ch = w >> 2;                  // column half: cols ch*128..+127
    int ar0 = r0 + g4, ar1 = ar0 + 8;

    float acc[16][4];
#pragma unroll
    for (int t = 0; t < 16; t++)
#pragma unroll
        for (int j = 0; j < 4; j++) acc[t][j] = 0.f;

#pragma unroll
    for (int hh = 0; hh < 2; hh++) {
        int h = ch * 2 + hh;
        unsigned int af[8][4];
#pragma unroll
        for (int ks = 0; ks < 8; ks++) {
            int kk = ks * 8;
            af[ks][0] = sA[ar0 * 268 + h * 67 + kk + tg];
            af[ks][1] = sA[ar1 * 268 + h * 67 + kk + tg];
            af[ks][2] = sA[ar0 * 268 + h * 67 + kk + tg + 4];
            af[ks][3] = sA[ar1 * 268 + h * 67 + kk + tg + 4];
        }
#pragma unroll
        for (int ks = 0; ks < 8; ks++) {
            int kk = ks * 8;
#pragma unroll
            for (int tt = 0; tt < 8; tt++) {
                int t = hh * 8 + tt;
                int c = ch * 128 + t * 8 + g4;
                unsigned int b0 = sB[c * 68 + kk + tg];
                unsigned int b1 = sB[c * 68 + kk + tg + 4];
                mma_tf32(acc[t][0], acc[t][1], acc[t][2], acc[t][3],
                         af[ks][0], af[ks][1], af[ks][2], af[ks][3], b0, b1);
            }
        }
    }

    // epilogue: bias + elu, write emb
    float* embp = g_emb + (size_t)slot * NF;
    bool v0 = (n0 + ar0) < N_, v1 = (n0 + ar1) < N_;
#pragma unroll
    for (int t = 0; t < 16; t++) {
        int c0 = ch * 128 + t * 8 + tg * 2;
        float bb0 = s_bias[c0], bb1 = s_bias[c0 + 1];
        if (v0) {
            float o0 = acc[t][0] + bb0, o1 = acc[t][1] + bb1;
            o0 = o0 > 0.f ? o0 : expm1f(o0);
            o1 = o1 > 0.f ? o1 : expm1f(o1);
            *(float2*)&embp[(size_t)(n0 + ar0) * F_ + c0] = make_float2(o0, o1);
        }
        if (v1) {
            float o2 = acc[t][2] + bb0, o3 = acc[t][3] + bb1;
            o2 = o2 > 0.f ? o2 : expm1f(o2);
            o3 = o3 > 0.f ? o3 : expm1f(o3);
            *(float2*)&embp[(size_t)(n0 + ar1) * F_ + c0] = make_float2(o2, o3);
        }
    }
}

// ---------------------------------------------------------------------------
// W1 prep: bf16x2-pack transposed-by-pairs: g_W1bf[p*128 + c] = (W1[2p][c], W1[2p+1][c])
// ---------------------------------------------------------------------------
__global__ void k_prepW1(const float* __restrict__ W1, int stage) {
    int j = blockIdx.x * 256 + threadIdx.x;
    if (j < (SAH_ * F_) / 2) {
        int p = j >> 7, c = j & 127;
        g_W1bf[j] = pack_bf2(W1[(2 * p) * SAH_ + c], W1[(2 * p + 1) * SAH_ + c]);
    }
    if (blockIdx.x == 0 && threadIdx.x < 4) g_wsum[stage][threadIdx.x] = 0.f;
}

// ---------------------------------------------------------------------------
// Semantic-attention score GEMM, bf16 m16n8k16 tensor cores.
// ---------------------------------------------------------------------------
__global__ void __launch_bounds__(256) k_wscore_tc(int sel, int layer, int stage,
                                                   const float* __restrict__ b1,
                                                   const float* __restrict__ w2) {
    __shared__ unsigned int sA[128 * 18];   // [row][pair] pad 18
    __shared__ unsigned int sB[128 * 18];   // [col][pair]
    __shared__ float s_b1[SAH_], s_w2[SAH_];
    __shared__ float sred[8];

    int tid = threadIdx.x, lane = tid & 31, w = tid >> 5;
    int m = blockIdx.y;
    int n0 = blockIdx.x * 128;
    const float* Z = sel ? (g_hl + (size_t)m * NF)
                         : (g_emb + (size_t)(layer * 3 + m) * NF);
    if (tid < SAH_) { s_b1[tid] = b1[tid]; s_w2[tid] = w2[tid]; }

    float acc[16][4];
#pragma unroll
    for (int t = 0; t < 16; t++)
#pragma unroll
        for (int j = 0; j < 4; j++) acc[t][j] = 0.f;

    int g4 = lane >> 2, tg = lane & 3;
    int ar0 = w * 16 + g4, ar1 = ar0 + 8;

    for (int f0 = 0; f0 < F_; f0 += 32) {
        int p0 = f0 >> 1;   // global pair base
        __syncthreads();
        // stage A: 128 rows x 16 pairs (fp32 -> bf16x2)
        for (int i = tid; i < 128 * 16; i += 256) {
            int r = i >> 4, p = i & 15;
            int n = n0 + r;
            float2 v = make_float2(0.f, 0.f);
            if (n < N_) v = *(const float2*)&Z[(size_t)n * F_ + f0 + p * 2];
            sA[r * 18 + p] = pack_bf2(v.x, v.y);
        }
        // stage B: 128 cols x 16 pairs from prepacked W1
        for (int i = tid; i < 128 * 16; i += 256) {
            int c = i & 127, p = i >> 7;
            sB[c * 18 + p] = g_W1bf[(p0 + p) * 128 + c];
        }
        __syncthreads();
#pragma unroll
        for (int s = 0; s < 2; s++) {
            int base = s * 8;
            unsigned int a0 = sA[ar0 * 18 + base + tg];
            unsigned int a1 = sA[ar1 * 18 + base + tg];
            unsigned int a2 = sA[ar0 * 18 + base + tg + 4];
            unsigned int a3 = sA[ar1 * 18 + base + tg + 4];
#pragma unroll
            for (int t = 0; t < 16; t++) {
                int c = t * 8 + g4;
                unsigned int b0 = sB[c * 18 + base + tg];
                unsigned int b1 = sB[c * 18 + base + tg + 4];
                mma_bf16(acc[t][0], acc[t][1], acc[t][2], acc[t][3],
                         a0, a1, a2, a3, b0, b1);
            }
        }
    }

    float tot = 0.f;
    bool v0 = (n0 + ar0) < N_, v1 = (n0 + ar1) < N_;
#pragma unroll
    for (int t = 0; t < 16; t++) {
        int c0 = t * 8 + tg * 2, c1 = c0 + 1;
        float bb0 = s_b1[c0], bb1 = s_b1[c1];
        float ww0 = s_w2[c0], ww1 = s_w2[c1];
        if (v0) tot += tanh_fast(acc[t][0] + bb0) * ww0 + tanh_fast(acc[t][1] + bb1) * ww1;
        if (v1) tot += tanh_fast(acc[t][2] + bb0) * ww0 + tanh_fast(acc[t][3] + bb1) * ww1;
    }
#pragma unroll
    for (int o = 16; o > 0; o >>= 1) tot += __shfl_xor_sync(0xffffffffu, tot, o);
    if (lane == 0) sred[w] = tot;
    __syncthreads();
    if (tid == 0) {
        float s = 0.f;
#pragma unroll
        for (int i = 0; i < 8; i++) s += sred[i];
        atomicAdd(&g_wsum[stage][m], s);
    }
}

__global__ void k_beta(int stage, int M) {
    if (threadIdx.x == 0) {
        float w[3];
        float mx = -1e30f;
        for (int m = 0; m < M; m++) { w[m] = g_wsum[stage][m] / (float)N_; mx = fmaxf(mx, w[m]); }
        float s = 0.f;
        for (int m = 0; m < M; m++) { w[m] = __expf(w[m] - mx); s += w[m]; }
        for (int m = 0; m < M; m++) g_beta[stage][m] = w[m] / s;
    }
}

__global__ void k_combine(int stage, float* __restrict__ dup) {
    size_t i = ((size_t)blockIdx.x * 256 + threadIdx.x) * 4;
    if (i >= NF) return;
    const float* base = (stage < 2) ? (g_emb + (size_t)stage * 3 * NF) : g_hl;
    float b0 = g_beta[stage][0], b1 = g_beta[stage][1], b2 = g_beta[stage][2];
    float4 v0 = *(const float4*)&base[i];
    float4 v1 = *(const float4*)&base[NF + i];
    float4 r;
    r.x = b0 * v0.x + b1 * v1.x;
    r.y = b0 * v0.y + b1 * v1.y;
    r.z = b0 * v0.z + b1 * v1.z;
    r.w = b0 * v0.w + b1 * v1.w;
    if (stage < 2) {
        float4 v2 = *(const float4*)&base[2 * NF + i];
        r.x += b2 * v2.x; r.y += b2 * v2.y; r.z += b2 * v2.z; r.w += b2 * v2.w;
    }
    float* out = (stage == 0) ? g_hl : (stage == 1 ? g_hl + NF : g_hfin);
    *(float4*)&out[i] = r;
    if (dup) *(float4*)&dup[i] = r;
}

// ---------------------------------------------------------------------------
// logits = h_final @ pred_W + pred_b
// ---------------------------------------------------------------------------
__global__ void k_pred(const float* __restrict__ W, const float* __restrict__ b,
                       float* __restrict__ out) {
    __shared__ float sW[F_ * OUT_];
    int tid = threadIdx.x;
    for (int i = tid; i < F_ * OUT_; i += 256) sW[i] = W[i];
    __syncthreads();
    int node = blockIdx.x * 16 + (tid >> 4);
    int o = tid & 15;
    if (node >= N_) return;
    const float* hr = g_hfin + (size_t)node * F_;
    float acc = b[o];
#pragma unroll 8
    for (int f = 0; f < F_; f++) acc += hr[f] * sW[f * OUT_ + o];
    out[(size_t)node * OUT_ + o] = acc;
}

// ---------------------------------------------------------------------------
// Host launcher — single stream, graph-capturable
// ---------------------------------------------------------------------------
extern "C" void kernel_launch(void* const* d_in, const int* in_sizes, int n_in,
                              void* d_out, int out_size) {
    const float* h = (const float*)d_in[0];
    G4 a;
    a.s[0] = (const int*)d_in[1]; a.d[0] = (const int*)d_in[2];
    a.s[1] = (const int*)d_in[3]; a.d[1] = (const int*)d_in[4];
    a.s[2] = (const int*)d_in[5]; a.d[2] = (const int*)d_in[6];
    a.s[3] = (const int*)d_in[7]; a.d[3] = (const int*)d_in[8];
    a.E[0] = in_sizes[1]; a.E[1] = in_sizes[3]; a.E[2] = in_sizes[5]; a.E[3] = in_sizes[7];
    const float* fcW = (const float*)d_in[10];
    const float* W[2]    = {(const float*)d_in[11], (const float*)d_in[18]};
    const float* al[2]   = {(const float*)d_in[12], (const float*)d_in[19]};
    const float* ar[2]   = {(const float*)d_in[13], (const float*)d_in[20]};
    const float* bb[2]   = {(const float*)d_in[14], (const float*)d_in[21]};
    const float* saW1[2] = {(const float*)d_in[15], (const float*)d_in[22]};
    const float* sab1[2] = {(const float*)d_in[16], (const float*)d_in[23]};
    const float* saw2[2] = {(const float*)d_in[17], (const float*)d_in[24]};
    const float* saW1f = (const float*)d_in[25];
    const float* sab1f = (const float*)d_in[26];
    const float* saw2f = (const float*)d_in[27];
    const float* predW = (const float*)d_in[28];
    const float* predb = (const float*)d_in[29];
    float* out = (float*)d_out;

    const int graphsel[2][3] = {{0, 1, 2}, {0, 1, 3}};
    const int Wtile = HID_ * F_;
    int maxE = a.E[0];
    for (int g = 1; g < 4; g++) if (a.E[g] > maxE) maxE = a.E[g];
    const int CMB = (int)((NF / 4 + 255) / 256);

    cudaFuncSetAttribute(k_post_tc, cudaFuncAttributeMaxDynamicSharedMemorySize, POST_SMEM);

    k_fc<<<(N_ + 15) / 16, 256>>>(h, fcW);

    // Batched CSR
    k_zerocnt4<<<SCB4, 256>>>();
    k_hist4<<<dim3((maxE + 255) / 256, 4), 256>>>(a);
    k_scan1b<<<SCB4, 256>>>();
    k_scan2b<<<1, 1024>>>();
    k_scan3b<<<SCB4, 256>>>();
    k_scatter4<<<dim3((maxE + 255) / 256, 4), 256>>>(a);

    for (int L = 0; L < 2; L++) {
        for (int m = 0; m < 3; m++) {
            int g = graphsel[L][m];
            int slot = L * 3 + m;
            const float* Wm = W[L] + (size_t)m * Wtile;
            k_eler3f<<<(N_ + 255) / 256, 256>>>(Wm, al[L] + m * F_, ar[L] + m * F_);
            k_conv2<<<(N_ + 7) / 8, 256>>>(g);
            k_post_tc<<<POSTB_N, 256, POST_SMEM>>>(Wm, bb[L] + m * F_, slot);
        }
        k_prepW1<<<(SAH_ * F_ / 2 + 255) / 256, 256>>>(saW1[L], L);
        k_wscore_tc<<<dim3(WSB_N, 3), 256>>>(0, L, L, sab1[L], saw2[L]);
        k_beta<<<1, 32>>>(L, 3);
        k_combine<<<CMB, 256>>>(L, nullptr);
    }

    k_prepW1<<<(SAH_ * F_ / 2 + 255) / 256, 256>>>(saW1f, 2);
    k_wscore_tc<<<dim3(WSB_N, 2), 256>>>(1, 0, 2, sab1f, saw2f);
    k_beta<<<1, 32>>>(2, 2);
    float* dup = (out_size >= N_ * (OUT_ + F_)) ? out + (size_t)N_ * OUT_ : nullptr;
    k_combine<<<CMB, 256>>>(2, dup);

    k_pred<<<(N_ + 15) / 16, 256>>>(predW, predb, out);
}

// round 10
// speedup vs baseline: 1.1301x; 1.1301x over previous
#include <cuda_runtime.h>
#include <math.h>
#include <float.h>

// ---------------------------------------------------------------------------
// Problem constants
// ---------------------------------------------------------------------------
constexpr int N_   = 50000;
constexpr int IN_  = 128;
constexpr int HID_ = 64;
constexpr int H_   = 4;
constexpr int F_   = 256;    // H*D
constexpr int OUT_ = 16;
constexpr int SAH_ = 128;
constexpr int EMAX_ = 800000;

constexpr size_t NF = (size_t)N_ * F_;
constexpr int NH = N_ * H_;
constexpr int SC4N = 4 * N_;
constexpr int SCB4 = (SC4N + 255) / 256;
constexpr int WSB_N = (N_ + 127) / 128;

// ---------------------------------------------------------------------------
// Device scratch
// ---------------------------------------------------------------------------
__device__ float g_x[(size_t)N_ * HID_];
__device__ __align__(16) float g_el[3 * NH];       // per-metapath
__device__ __align__(16) float g_er[3 * NH];
__device__ float g_agg[3 * NF];                    // per-metapath [n][k*4+h]
__device__ float g_emb[6 * NF];
__device__ float g_hl[2 * NF];
__device__ float g_hfin[NF];
__device__ float g_wsum[3][4];
__device__ float g_beta[3][4];
__device__ unsigned int g_W1bf[(SAH_ * F_) / 2];   // bf16x2, [pair p][col c]

// Batched CSR scratch
__device__ int g_cnt4[SC4N];
__device__ int g_cursor4[SC4N];
__device__ int g_prefix[SC4N + 1];
__device__ int g_esrcF[4 * EMAX_];
__device__ int g_bsum[SCB4];
__device__ int g_boff[SCB4];

struct G4 { const int* s[4]; const int* d[4]; int E[4]; };

// ---------------------------------------------------------------------------
// Low-level helpers
// ---------------------------------------------------------------------------
__device__ __forceinline__ unsigned int pack_bf2(float lo, float hi) {
    unsigned int r;
    asm("cvt.rn.bf16x2.f32 %0, %1, %2;" : "=r"(r) : "f"(hi), "f"(lo));
    return r;
}
__device__ __forceinline__ float tanh_fast(float x) {
    float r;
    asm("tanh.approx.f32 %0, %1;" : "=f"(r) : "f"(x));
    return r;
}
__device__ __forceinline__ void mma_bf16(float& d0, float& d1, float& d2, float& d3,
                                         unsigned int a0, unsigned int a1,
                                         unsigned int a2, unsigned int a3,
                                         unsigned int b0, unsigned int b1) {
    asm("mma.sync.aligned.m16n8k16.row.col.f32.bf16.bf16.f32 "
        "{%0,%1,%2,%3}, {%4,%5,%6,%7}, {%8,%9}, {%0,%1,%2,%3};"
        : "+f"(d0), "+f"(d1), "+f"(d2), "+f"(d3)
        : "r"(a0), "r"(a1), "r"(a2), "r"(a3), "r"(b0), "r"(b1));
}

// ---------------------------------------------------------------------------
// x = h @ fc_W   [N,128] @ [128,64]
// ---------------------------------------------------------------------------
__global__ void k_fc(const float* __restrict__ h, const float* __restrict__ W) {
    __shared__ __align__(16) float sW[IN_ * HID_];
    __shared__ __align__(16) float sh[16 * IN_];
    int tid = threadIdx.x;
    for (int i = tid; i < IN_ * HID_; i += 256) sW[i] = W[i];
    int row0 = blockIdx.x * 16;
    for (int i = tid; i < 16 * IN_; i += 256) {
        int r = i >> 7, k = i & 127;
        sh[i] = (row0 + r < N_) ? h[(size_t)(row0 + r) * IN_ + k] : 0.f;
    }
    __syncthreads();
    int col = tid & 63;
    for (int rr = tid >> 6; rr < 16; rr += 4) {
        float acc = 0.f;
#pragma unroll
        for (int k = 0; k < IN_; k += 4) {
            float4 hv = *(const float4*)&sh[rr * IN_ + k];
            acc += hv.x * sW[k * HID_ + col] + hv.y * sW[(k + 1) * HID_ + col]
                 + hv.z * sW[(k + 2) * HID_ + col] + hv.w * sW[(k + 3) * HID_ + col];
        }
        if (row0 + rr < N_) g_x[(size_t)(row0 + rr) * HID_ + col] = acc;
    }
}

// ---------------------------------------------------------------------------
// Fused prew + eler, batched over 3 metapaths (blockIdx.y = m)
// ---------------------------------------------------------------------------
__global__ void __launch_bounds__(256) k_eler3f(const float* __restrict__ Wl,
                                                const float* __restrict__ all,
                                                const float* __restrict__ arl) {
    __shared__ float swt[HID_ * 8];
    int m = blockIdx.y;
    const float* W = Wl + (size_t)m * HID_ * F_;
    const float* al = all + m * F_;
    const float* ar = arl + m * F_;
    float* elb = g_el + m * NH;
    float* erb = g_er + m * NH;
    int tid = threadIdx.x;
    {
        int k = tid >> 2, h = tid & 3;
        const float* wr = W + k * F_ + h * 64;
        const float* alr = al + h * 64;
        const float* arr = ar + h * 64;
        float a = 0.f, b = 0.f;
#pragma unroll 8
        for (int d = 0; d < 64; d++) { a += wr[d] * alr[d]; b += wr[d] * arr[d]; }
        swt[k * 8 + h] = a;
        swt[k * 8 + 4 + h] = b;
    }
    __syncthreads();
    int o = tid & 7;
    int n0 = blockIdx.x * 256;
    for (int pass = 0; pass < 8; pass++) {
        int n = n0 + pass * 32 + (tid >> 3);
        if (n >= N_) break;
        const float4* xr = (const float4*)(g_x + (size_t)n * HID_);
        float acc = 0.f;
#pragma unroll
        for (int q = 0; q < 16; q++) {
            float4 v = xr[q];
            acc += v.x * swt[(q * 4 + 0) * 8 + o] + v.y * swt[(q * 4 + 1) * 8 + o]
                 + v.z * swt[(q * 4 + 2) * 8 + o] + v.w * swt[(q * 4 + 3) * 8 + o];
        }
        if (o < 4) elb[n * 4 + o] = acc;
        else       erb[n * 4 + (o - 4)] = acc;
    }
}

// ---------------------------------------------------------------------------
// Batched CSR construction
// ---------------------------------------------------------------------------
__global__ void k_zerocnt4() {
    int i = blockIdx.x * 256 + threadIdx.x;
    if (i < SC4N) g_cnt4[i] = 0;
}
__global__ void k_hist4(G4 a) {
    int g = blockIdx.y;
    int i = blockIdx.x * 256 + threadIdx.x;
    if (i < a.E[g]) atomicAdd(&g_cnt4[g * N_ + a.d[g][i]], 1);
}

template <int NW>
__device__ __forceinline__ int scan_excl(int v, int tid, int* total) {
    int lane = tid & 31, w = tid >> 5;
    int x = v;
#pragma unroll
    for (int o = 1; o < 32; o <<= 1) {
        int y = __shfl_up_sync(0xffffffffu, x, o);
        if (lane >= o) x += y;
    }
    __shared__ int ws[NW];
    if (lane == 31) ws[w] = x;
    __syncthreads();
    if (w == 0) {
        int s = (lane < NW) ? ws[lane] : 0;
#pragma unroll
        for (int o = 1; o < NW; o <<= 1) {
            int y = __shfl_up_sync(0xffffffffu, s, o);
            if (lane >= o) s += y;
        }
        if (lane < NW) ws[lane] = s;
    }
    __syncthreads();
    int base = (w > 0) ? ws[w - 1] : 0;
    *total = ws[NW - 1];
    return base + x - v;
}

__global__ void k_scan1b() {
    int tid = threadIdx.x, b = blockIdx.x;
    int i = b * 256 + tid;
    int v = (i < SC4N) ? g_cnt4[i] : 0;
    int total;
    int excl = scan_excl<8>(v, tid, &total);
    if (i < SC4N) g_prefix[i] = excl;
    if (tid == 0) g_bsum[b] = total;
}
__global__ void k_scan2b() {
    int tid = threadIdx.x;
    int v = (tid < SCB4) ? g_bsum[tid] : 0;
    int total;
    int excl = scan_excl<32>(v, tid, &total);
    if (tid < SCB4) g_boff[tid] = excl;
    if (tid == 0) g_prefix[SC4N] = total;
}
__global__ void k_scan3b() {
    int i = blockIdx.x * 256 + threadIdx.x;
    if (i < SC4N) {
        int r = g_prefix[i] + g_boff[i >> 8];
        g_prefix[i] = r;
        g_cursor4[i] = r;
    }
}
__global__ void k_scatter4(G4 a) {
    int g = blockIdx.y;
    int i = blockIdx.x * 256 + threadIdx.x;
    if (i >= a.E[g]) return;
    int d = a.d[g][i];
    int pos = atomicAdd(&g_cursor4[g * N_ + d], 1);
    g_esrcF[pos] = a.s[g][i];
}

// ---------------------------------------------------------------------------
// x-space gather-accumulate
// ---------------------------------------------------------------------------
__device__ __forceinline__ void gather_acc2(const int* __restrict__ ssrc,
                                            const float4* __restrict__ salpha,
                                            int cnt, int lane, float acc[8]) {
    int i = 0;
    for (; i + 4 <= cnt; i += 4) {
        int s0 = ssrc[i], s1 = ssrc[i + 1], s2 = ssrc[i + 2], s3 = ssrc[i + 3];
        float4 a0 = salpha[i], a1 = salpha[i + 1], a2 = salpha[i + 2], a3 = salpha[i + 3];
        float2 x0 = *(const float2*)(g_x + (size_t)s0 * HID_ + lane * 2);
        float2 x1 = *(const float2*)(g_x + (size_t)s1 * HID_ + lane * 2);
        float2 x2 = *(const float2*)(g_x + (size_t)s2 * HID_ + lane * 2);
        float2 x3 = *(const float2*)(g_x + (size_t)s3 * HID_ + lane * 2);
        acc[0] += a0.x * x0.x; acc[1] += a0.x * x0.y;
        acc[2] += a0.y * x0.x; acc[3] += a0.y * x0.y;
        acc[4] += a0.z * x0.x; acc[5] += a0.z * x0.y;
        acc[6] += a0.w * x0.x; acc[7] += a0.w * x0.y;
        acc[0] += a1.x * x1.x; acc[1] += a1.x * x1.y;
        acc[2] += a1.y * x1.x; acc[3] += a1.y * x1.y;
        acc[4] += a1.z * x1.x; acc[5] += a1.z * x1.y;
        acc[6] += a1.w * x1.x; acc[7] += a1.w * x1.y;
        acc[0] += a2.x * x2.x; acc[1] += a2.x * x2.y;
        acc[2] += a2.y * x2.x; acc[3] += a2.y * x2.y;
        acc[4] += a2.z * x2.x; acc[5] += a2.z * x2.y;
        acc[6] += a2.w * x2.x; acc[7] += a2.w * x2.y;
        acc[0] += a3.x * x3.x; acc[1] += a3.x * x3.y;
        acc[2] += a3.y * x3.x; acc[3] += a3.y * x3.y;
        acc[4] += a3.z * x3.x; acc[5] += a3.z * x3.y;
        acc[6] += a3.w * x3.x; acc[7] += a3.w * x3.y;
    }
    for (; i < cnt; i++) {
        int s = ssrc[i];
        float4 a = salpha[i];
        float2 xv = *(const float2*)(g_x + (size_t)s * HID_ + lane * 2);
        acc[0] += a.x * xv.x; acc[1] += a.x * xv.y;
        acc[2] += a.y * xv.x; acc[3] += a.y * xv.y;
        acc[4] += a.z * xv.x; acc[5] += a.z * xv.y;
        acc[6] += a.w * xv.x; acc[7] += a.w * xv.y;
    }
}

// ---------------------------------------------------------------------------
// GAT conv in x-space — WARP per dst node, batched over 3 metapaths (y = m)
// ---------------------------------------------------------------------------
__global__ void __launch_bounds__(256) k_conv2b(int ga, int gb, int gc) {
    __shared__ int s_src[8][32];
    __shared__ __align__(16) float4 s_alpha[8][32];

    int m = blockIdx.y;
    int gi = (m == 0) ? ga : (m == 1) ? gb : gc;
    const float* elb = g_el + m * NH;
    const float* erb = g_er + m * NH;
    float* aggb = g_agg + (size_t)m * NF;

    int tid = threadIdx.x, lane = tid & 31, w = tid >> 5;
    int n = blockIdx.x * 8 + w;
    if (n >= N_) return;

    int e0 = g_prefix[gi * N_ + n], e1 = g_prefix[gi * N_ + n + 1];
    int deg = e1 - e0;

    float4 ern = *(const float4*)(erb + n * 4);
    float acc[8] = {0.f, 0.f, 0.f, 0.f, 0.f, 0.f, 0.f, 0.f};

    if (deg > 0 && deg <= 32) {
        int s = -1;
        float v0 = -FLT_MAX, v1 = -FLT_MAX, v2 = -FLT_MAX, v3 = -FLT_MAX;
        if (lane < deg) {
            s = g_esrcF[e0 + lane];
            float4 els = *(const float4*)(elb + s * 4);
            v0 = els.x + ern.x; v0 = v0 > 0.f ? v0 : 0.2f * v0;
            v1 = els.y + ern.y; v1 = v1 > 0.f ? v1 : 0.2f * v1;
            v2 = els.z + ern.z; v2 = v2 > 0.f ? v2 : 0.2f * v2;
            v3 = els.w + ern.w; v3 = v3 > 0.f ? v3 : 0.2f * v3;
        }
        float m0 = v0, m1 = v1, m2 = v2, m3 = v3;
#pragma unroll
        for (int o = 16; o > 0; o >>= 1) {
            m0 = fmaxf(m0, __shfl_xor_sync(0xffffffffu, m0, o));
            m1 = fmaxf(m1, __shfl_xor_sync(0xffffffffu, m1, o));
            m2 = fmaxf(m2, __shfl_xor_sync(0xffffffffu, m2, o));
            m3 = fmaxf(m3, __shfl_xor_sync(0xffffffffu, m3, o));
        }
        float e0f = (lane < deg) ? __expf(v0 - m0) : 0.f;
        float e1f = (lane < deg) ? __expf(v1 - m1) : 0.f;
        float e2f = (lane < deg) ? __expf(v2 - m2) : 0.f;
        float e3f = (lane < deg) ? __expf(v3 - m3) : 0.f;
        float s0 = e0f, s1 = e1f, s2 = e2f, s3 = e3f;
#pragma unroll
        for (int o = 16; o > 0; o >>= 1) {
            s0 += __shfl_xor_sync(0xffffffffu, s0, o);
            s1 += __shfl_xor_sync(0xffffffffu, s1, o);
            s2 += __shfl_xor_sync(0xffffffffu, s2, o);
            s3 += __shfl_xor_sync(0xffffffffu, s3, o);
        }
        s_src[w][lane] = s;
        s_alpha[w][lane] = make_float4(e0f / s0, e1f / s1, e2f / s2, e3f / s3);
        __syncwarp();
        gather_acc2(s_src[w], s_alpha[w], deg, lane, acc);
    } else if (deg > 32) {
        float mx[4] = {-FLT_MAX, -FLT_MAX, -FLT_MAX, -FLT_MAX};
        float sm[4] = {0.f, 0.f, 0.f, 0.f};
        for (int e = e0 + lane; e < e1; e += 32) {
            int s = g_esrcF[e];
            float4 els = *(const float4*)(elb + s * 4);
            float v[4];
            v[0] = els.x + ern.x; v[1] = els.y + ern.y;
            v[2] = els.z + ern.z; v[3] = els.w + ern.w;
#pragma unroll
            for (int h = 0; h < 4; h++) {
                float vv = v[h] > 0.f ? v[h] : 0.2f * v[h];
                float nm = fmaxf(mx[h], vv);
                sm[h] = sm[h] * __expf(mx[h] - nm) + __expf(vv - nm);
                mx[h] = nm;
            }
        }
#pragma unroll
        for (int h = 0; h < 4; h++) {
#pragma unroll
            for (int o = 16; o > 0; o >>= 1) {
                float om = __shfl_xor_sync(0xffffffffu, mx[h], o);
                float os = __shfl_xor_sync(0xffffffffu, sm[h], o);
                float nm = fmaxf(mx[h], om);
                sm[h] = sm[h] * __expf(mx[h] - nm) + os * __expf(om - nm);
                mx[h] = nm;
            }
        }
        float inv[4];
#pragma unroll
        for (int h = 0; h < 4; h++) inv[h] = 1.f / sm[h];

        for (int base = 0; base < deg; base += 32) {
            int cnt = min(32, deg - base);
            int s = -1;
            float4 al4 = make_float4(0.f, 0.f, 0.f, 0.f);
            if (lane < cnt) {
                s = g_esrcF[e0 + base + lane];
                float4 els = *(const float4*)(elb + s * 4);
                float v0 = els.x + ern.x; v0 = v0 > 0.f ? v0 : 0.2f * v0;
                float v1 = els.y + ern.y; v1 = v1 > 0.f ? v1 : 0.2f * v1;
                float v2 = els.z + ern.z; v2 = v2 > 0.f ? v2 : 0.2f * v2;
                float v3 = els.w + ern.w; v3 = v3 > 0.f ? v3 : 0.2f * v3;
                al4 = make_float4(__expf(v0 - mx[0]) * inv[0], __expf(v1 - mx[1]) * inv[1],
                                  __expf(v2 - mx[2]) * inv[2], __expf(v3 - mx[3]) * inv[3]);
            }
            __syncwarp();
            s_src[w][lane] = s;
            s_alpha[w][lane] = al4;
            __syncwarp();
            gather_acc2(s_src[w], s_alpha[w], cnt, lane, acc);
        }
    }

    float4* op = (float4*)(aggb + (size_t)n * F_ + (lane * 2) * 4);
    op[0] = make_float4(acc[0], acc[2], acc[4], acc[6]);
    op[1] = make_float4(acc[1], acc[3], acc[5], acc[7]);
}

// ---------------------------------------------------------------------------
// Post-GEMM (fp32, register weights), batched over 3 metapaths (y = m)
// emb[n,h,d] = elu( sum_k agg[n,h,k] * W[k,h,d] + b[h,d] )
// ---------------------------------------------------------------------------
__global__ void __launch_bounds__(256) k_post(const float* __restrict__ Wl,
                                              const float* __restrict__ bbl,
                                              int L) {
    __shared__ float sagg[32 * 272];   // [r][h*68 + k]
    int m = blockIdx.y;
    const float* W = Wl + (size_t)m * HID_ * F_;
    const float* bias = bbl + m * F_;
    const float* aggb = g_agg + (size_t)m * NF;
    int slot = L * 3 + m;

    int tid = threadIdx.x;
    int h = tid >> 6, d = tid & 63;
    float wreg[HID_];
#pragma unroll
    for (int k = 0; k < HID_; k++) wreg[k] = W[k * F_ + h * 64 + d];
    float bv = bias[tid];
    int n0 = blockIdx.x * 32;
    for (int idx = tid; idx < 32 * 256; idx += 256) {
        int r = idx >> 8, j = idx & 255;
        int kk = j >> 2, hh = j & 3;
        float v = (n0 + r < N_) ? aggb[(size_t)(n0 + r) * F_ + j] : 0.f;
        sagg[r * 272 + hh * 68 + kk] = v;
    }
    __syncthreads();
    int rmax = min(32, N_ - n0);
    for (int r = 0; r < rmax; r++) {
        const float4* ap = (const float4*)(sagg + r * 272 + h * 68);
        float acc = 0.f;
#pragma unroll
        for (int q = 0; q < 16; q++) {
            float4 v = ap[q];
            acc += v.x * wreg[q * 4] + v.y * wreg[q * 4 + 1]
                 + v.z * wreg[q * 4 + 2] + v.w * wreg[q * 4 + 3];
        }
        float o = acc + bv;
        g_emb[(size_t)slot * NF + (size_t)(n0 + r) * F_ + tid] = o > 0.f ? o : expm1f(o);
    }
}

// ---------------------------------------------------------------------------
// W1 prep: bf16x2-pack (pairs of rows), zero wsum[stage]
// ---------------------------------------------------------------------------
__global__ void k_prepW1(const float* __restrict__ W1, int stage) {
    int j = blockIdx.x * 256 + threadIdx.x;
    if (j < (SAH_ * F_) / 2) {
        int p = j >> 7, c = j & 127;
        g_W1bf[j] = pack_bf2(W1[(2 * p) * SAH_ + c], W1[(2 * p + 1) * SAH_ + c]);
    }
    if (blockIdx.x == 0 && threadIdx.x < 4) g_wsum[stage][threadIdx.x] = 0.f;
}

// ---------------------------------------------------------------------------
// Semantic-attention score GEMM, bf16 m16n8k16 tensor cores.
// ---------------------------------------------------------------------------
__global__ void __launch_bounds__(256) k_wscore_tc(int sel, int layer, int stage,
                                                   const float* __restrict__ b1,
                                                   const float* __restrict__ w2) {
    __shared__ unsigned int sA[128 * 18];
    __shared__ unsigned int sB[128 * 18];
    __shared__ float s_b1[SAH_], s_w2[SAH_];
    __shared__ float sred[8];

    int tid = threadIdx.x, lane = tid & 31, w = tid >> 5;
    int m = blockIdx.y;
    int n0 = blockIdx.x * 128;
    const float* Z = sel ? (g_hl + (size_t)m * NF)
                         : (g_emb + (size_t)(layer * 3 + m) * NF);
    if (tid < SAH_) { s_b1[tid] = b1[tid]; s_w2[tid] = w2[tid]; }

    float acc[16][4];
#pragma unroll
    for (int t = 0; t < 16; t++)
#pragma unroll
        for (int j = 0; j < 4; j++) acc[t][j] = 0.f;

    int g4 = lane >> 2, tg = lane & 3;
    int ar0 = w * 16 + g4, ar1 = ar0 + 8;

    for (int f0 = 0; f0 < F_; f0 += 32) {
        int p0 = f0 >> 1;
        __syncthreads();
        for (int i = tid; i < 128 * 16; i += 256) {
            int r = i >> 4, p = i & 15;
            int n = n0 + r;
            float2 v = make_float2(0.f, 0.f);
            if (n < N_) v = *(const float2*)&Z[(size_t)n * F_ + f0 + p * 2];
            sA[r * 18 + p] = pack_bf2(v.x, v.y);
        }
        for (int i = tid; i < 128 * 16; i += 256) {
            int c = i & 127, p = i >> 7;
            sB[c * 18 + p] = g_W1bf[(p0 + p) * 128 + c];
        }
        __syncthreads();
#pragma unroll
        for (int s = 0; s < 2; s++) {
            int base = s * 8;
            unsigned int a0 = sA[ar0 * 18 + base + tg];
            unsigned int a1 = sA[ar1 * 18 + base + tg];
            unsigned int a2 = sA[ar0 * 18 + base + tg + 4];
            unsigned int a3 = sA[ar1 * 18 + base + tg + 4];
#pragma unroll
            for (int t = 0; t < 16; t++) {
                int c = t * 8 + g4;
                unsigned int b0 = sB[c * 18 + base + tg];
                unsigned int b1 = sB[c * 18 + base + tg + 4];
                mma_bf16(acc[t][0], acc[t][1], acc[t][2], acc[t][3],
                         a0, a1, a2, a3, b0, b1);
            }
        }
    }

    float tot = 0.f;
    bool v0 = (n0 + ar0) < N_, v1 = (n0 + ar1) < N_;
#pragma unroll
    for (int t = 0; t < 16; t++) {
        int c0 = t * 8 + tg * 2, c1 = c0 + 1;
        float bb0 = s_b1[c0], bb1 = s_b1[c1];
        float ww0 = s_w2[c0], ww1 = s_w2[c1];
        if (v0) tot += tanh_fast(acc[t][0] + bb0) * ww0 + tanh_fast(acc[t][1] + bb1) * ww1;
        if (v1) tot += tanh_fast(acc[t][2] + bb0) * ww0 + tanh_fast(acc[t][3] + bb1) * ww1;
    }
#pragma unroll
    for (int o = 16; o > 0; o >>= 1) tot += __shfl_xor_sync(0xffffffffu, tot, o);
    if (lane == 0) sred[w] = tot;
    __syncthreads();
    if (tid == 0) {
        float s = 0.f;
#pragma unroll
        for (int i = 0; i < 8; i++) s += sred[i];
        atomicAdd(&g_wsum[stage][m], s);
    }
}

__global__ void k_beta(int stage, int M) {
    if (threadIdx.x == 0) {
        float w[3];
        float mx = -1e30f;
        for (int m = 0; m < M; m++) { w[m] = g_wsum[stage][m] / (float)N_; mx = fmaxf(mx, w[m]); }
        float s = 0.f;
        for (int m = 0; m < M; m++) { w[m] = __expf(w[m] - mx); s += w[m]; }
        for (int m = 0; m < M; m++) g_beta[stage][m] = w[m] / s;
    }
}

__global__ void k_combine(int stage, float* __restrict__ dup) {
    size_t i = ((size_t)blockIdx.x * 256 + threadIdx.x) * 4;
    if (i >= NF) return;
    const float* base = (stage < 2) ? (g_emb + (size_t)stage * 3 * NF) : g_hl;
    float b0 = g_beta[stage][0], b1 = g_beta[stage][1], b2 = g_beta[stage][2];
    float4 v0 = *(const float4*)&base[i];
    float4 v1 = *(const float4*)&base[NF + i];
    float4 r;
    r.x = b0 * v0.x + b1 * v1.x;
    r.y = b0 * v0.y + b1 * v1.y;
    r.z = b0 * v0.z + b1 * v1.z;
    r.w = b0 * v0.w + b1 * v1.w;
    if (stage < 2) {
        float4 v2 = *(const float4*)&base[2 * NF + i];
        r.x += b2 * v2.x; r.y += b2 * v2.y; r.z += b2 * v2.z; r.w += b2 * v2.w;
    }
    float* out = (stage == 0) ? g_hl : (stage == 1 ? g_hl + NF : g_hfin);
    *(float4*)&out[i] = r;
    if (dup) *(float4*)&dup[i] = r;
}

// ---------------------------------------------------------------------------
// logits = h_final @ pred_W + pred_b
// ---------------------------------------------------------------------------
__global__ void k_pred(const float* __restrict__ W, const float* __restrict__ b,
                       float* __restrict__ out) {
    __shared__ float sW[F_ * OUT_];
    int tid = threadIdx.x;
    for (int i = tid; i < F_ * OUT_; i += 256) sW[i] = W[i];
    __syncthreads();
    int node = blockIdx.x * 16 + (tid >> 4);
    int o = tid & 15;
    if (node >= N_) return;
    const float* hr = g_hfin + (size_t)node * F_;
    float acc = b[o];
#pragma unroll 8
    for (int f = 0; f < F_; f++) acc += hr[f] * sW[f * OUT_ + o];
    out[(size_t)node * OUT_ + o] = acc;
}

// ---------------------------------------------------------------------------
// Host launcher — single stream, graph-capturable
// ---------------------------------------------------------------------------
extern "C" void kernel_launch(void* const* d_in, const int* in_sizes, int n_in,
                              void* d_out, int out_size) {
    const float* h = (const float*)d_in[0];
    G4 a;
    a.s[0] = (const int*)d_in[1]; a.d[0] = (const int*)d_in[2];
    a.s[1] = (const int*)d_in[3]; a.d[1] = (const int*)d_in[4];
    a.s[2] = (const int*)d_in[5]; a.d[2] = (const int*)d_in[6];
    a.s[3] = (const int*)d_in[7]; a.d[3] = (const int*)d_in[8];
    a.E[0] = in_sizes[1]; a.E[1] = in_sizes[3]; a.E[2] = in_sizes[5]; a.E[3] = in_sizes[7];
    const float* fcW = (const float*)d_in[10];
    const float* W[2]    = {(const float*)d_in[11], (const float*)d_in[18]};
    const float* al[2]   = {(const float*)d_in[12], (const float*)d_in[19]};
    const float* ar[2]   = {(const float*)d_in[13], (const float*)d_in[20]};
    const float* bb[2]   = {(const float*)d_in[14], (const float*)d_in[21]};
    const float* saW1[2] = {(const float*)d_in[15], (const float*)d_in[22]};
    const float* sab1[2] = {(const float*)d_in[16], (const float*)d_in[23]};
    const float* saw2[2] = {(const float*)d_in[17], (const float*)d_in[24]};
    const float* saW1f = (const float*)d_in[25];
    const float* sab1f = (const float*)d_in[26];
    const float* saw2f = (const float*)d_in[27];
    const float* predW = (const float*)d_in[28];
    const float* predb = (const float*)d_in[29];
    float* out = (float*)d_out;

    const int graphsel[2][3] = {{0, 1, 2}, {0, 1, 3}};
    int maxE = a.E[0];
    for (int g = 1; g < 4; g++) if (a.E[g] > maxE) maxE = a.E[g];
    const int CMB = (int)((NF / 4 + 255) / 256);

    k_fc<<<(N_ + 15) / 16, 256>>>(h, fcW);

    // Batched CSR
    k_zerocnt4<<<SCB4, 256>>>();
    k_hist4<<<dim3((maxE + 255) / 256, 4), 256>>>(a);
    k_scan1b<<<SCB4, 256>>>();
    k_scan2b<<<1, 1024>>>();
    k_scan3b<<<SCB4, 256>>>();
    k_scatter4<<<dim3((maxE + 255) / 256, 4), 256>>>(a);

    for (int L = 0; L < 2; L++) {
        k_eler3f<<<dim3((N_ + 255) / 256, 3), 256>>>(W[L], al[L], ar[L]);
        k_conv2b<<<dim3((N_ + 7) / 8, 3), 256>>>(graphsel[L][0], graphsel[L][1], graphsel[L][2]);
        k_post<<<dim3((N_ + 31) / 32, 3), 256>>>(W[L], bb[L], L);
        k_prepW1<<<(SAH_ * F_ / 2 + 255) / 256, 256>>>(saW1[L], L);
        k_wscore_tc<<<dim3(WSB_N, 3), 256>>>(0, L, L, sab1[L], saw2[L]);
        k_beta<<<1, 32>>>(L, 3);
        k_combine<<<CMB, 256>>>(L, nullptr);
    }

    k_prepW1<<<(SAH_ * F_ / 2 + 255) / 256, 256>>>(saW1f, 2);
    k_wscore_tc<<<dim3(WSB_N, 2), 256>>>(1, 0, 2, sab1f, saw2f);
    k_beta<<<1, 32>>>(2, 2);
    float* dup = (out_size >= N_ * (OUT_ + F_)) ? out + (size_t)N_ * OUT_ : nullptr;
    k_combine<<<CMB, 256>>>(2, dup);

    k_pred<<<(N_ + 15) / 16, 256>>>(predW, predb, out);
}